// round 2
// baseline (speedup 1.0000x reference)
#include <cuda_runtime.h>

// Problem dims (fixed by the dataset)
#define BB 4
#define SS 2048
#define HH 1024
#define LL 4
#define FF 4096
#define NN (BB*SS)          // 8192 token rows
#define NCHUNK 32
#define CLEN (SS/NCHUNK)    // 64

// ---------------- scratch (no allocations allowed) ----------------
__device__ float g_h  [(size_t)NN*HH];
__device__ float g_tre[(size_t)NN*HH];
__device__ float g_tim[(size_t)NN*HH];
__device__ float g_y  [(size_t)NN*HH];
__device__ float g_f  [(size_t)NN*FF];
__device__ float2 g_carry[BB*NCHUNK*HH];

// ---------------- embedding ----------------
__global__ void embed_kernel(const int* __restrict__ ids, const float* __restrict__ we,
                             const float* __restrict__ pe, float* __restrict__ out)
{
    int e = blockIdx.x * blockDim.x + threadIdx.x;   // one float4 per thread
    int n  = e >> 8;                                  // HH/4 = 256 quads per row
    int hq = (e & 255) << 2;
    int s  = n & (SS - 1);
    int id = ids[n];
    float4 w = *(const float4*)(we + (size_t)id * HH + hq);
    float4 p = *(const float4*)(pe + (size_t)s  * HH + hq);
    *(float4*)(out + (size_t)n * HH + hq) =
        make_float4(w.x + p.x, w.y + p.y, w.z + p.z, w.w + p.w);
}

// ---------------- GEMM 1: Bu_re/Bu_im = (h @ B^T) * gamma ----------------
// A[N,K] row-major, W[M,K] row-major (NT). dual output with shared A tile.
__global__ __launch_bounds__(256) void gemm_bu(
    const float* __restrict__ A, const float* __restrict__ WRe, const float* __restrict__ WIm,
    const float* __restrict__ nul,
    float* __restrict__ ORe, float* __restrict__ OIm, int M, int K)
{
    __shared__ __align__(16) float As[16*68], Wr[16*68], Wi[16*68];
    const int tid = threadIdx.x;
    const int tx = tid & 15, ty = tid >> 4;
    const int n0 = blockIdx.y << 6, m0 = blockIdx.x << 6;
    const int lr = tid >> 2;
    const int lk = (tid & 3) << 2;
    const float* Ap  = A   + (size_t)(n0 + lr) * K + lk;
    const float* Wrp = WRe + (size_t)(m0 + lr) * K + lk;
    const float* Wip = WIm + (size_t)(m0 + lr) * K + lk;
    float aR[4][4] = {}, aI[4][4] = {};
    for (int k0 = 0; k0 < K; k0 += 16) {
        float4 a  = *(const float4*)(Ap  + k0);
        float4 wr = *(const float4*)(Wrp + k0);
        float4 wi = *(const float4*)(Wip + k0);
        __syncthreads();
        As[(lk+0)*68+lr]=a.x;  As[(lk+1)*68+lr]=a.y;  As[(lk+2)*68+lr]=a.z;  As[(lk+3)*68+lr]=a.w;
        Wr[(lk+0)*68+lr]=wr.x; Wr[(lk+1)*68+lr]=wr.y; Wr[(lk+2)*68+lr]=wr.z; Wr[(lk+3)*68+lr]=wr.w;
        Wi[(lk+0)*68+lr]=wi.x; Wi[(lk+1)*68+lr]=wi.y; Wi[(lk+2)*68+lr]=wi.z; Wi[(lk+3)*68+lr]=wi.w;
        __syncthreads();
        #pragma unroll
        for (int kk = 0; kk < 16; kk++) {
            float4 av  = *(const float4*)&As[kk*68 + (ty<<2)];
            float4 wrv = *(const float4*)&Wr[kk*68 + (tx<<2)];
            float4 wiv = *(const float4*)&Wi[kk*68 + (tx<<2)];
            float avv[4] = {av.x, av.y, av.z, av.w};
            float wr4[4] = {wrv.x, wrv.y, wrv.z, wrv.w};
            float wi4[4] = {wiv.x, wiv.y, wiv.z, wiv.w};
            #pragma unroll
            for (int i = 0; i < 4; i++)
                #pragma unroll
                for (int j = 0; j < 4; j++) {
                    aR[i][j] = fmaf(avv[i], wr4[j], aR[i][j]);
                    aI[i][j] = fmaf(avv[i], wi4[j], aI[i][j]);
                }
        }
    }
    float gma[4];
    #pragma unroll
    for (int j = 0; j < 4; j++) {
        int u = m0 + (tx<<2) + j;
        gma[j] = sqrtf(fmaxf(1.f - expf(-2.f * expf(nul[u])), 0.f));
    }
    #pragma unroll
    for (int i = 0; i < 4; i++) {
        size_t o = (size_t)(n0 + (ty<<2) + i) * M + m0 + (tx<<2);
        *(float4*)(ORe + o) = make_float4(aR[i][0]*gma[0], aR[i][1]*gma[1], aR[i][2]*gma[2], aR[i][3]*gma[3]);
        *(float4*)(OIm + o) = make_float4(aI[i][0]*gma[0], aI[i][1]*gma[1], aI[i][2]*gma[2], aI[i][3]*gma[3]);
    }
}

// ---------------- GEMM 2: y = re @ C_re^T - im @ C_im^T ----------------
__global__ __launch_bounds__(256) void gemm_y(
    const float* __restrict__ ARe, const float* __restrict__ AIm,
    const float* __restrict__ WRe, const float* __restrict__ WIm,
    float* __restrict__ O, int M, int K)
{
    __shared__ __align__(16) float Ar[16*68], Ai[16*68], Wr[16*68], Wi[16*68];
    const int tid = threadIdx.x;
    const int tx = tid & 15, ty = tid >> 4;
    const int n0 = blockIdx.y << 6, m0 = blockIdx.x << 6;
    const int lr = tid >> 2;
    const int lk = (tid & 3) << 2;
    const float* Arp = ARe + (size_t)(n0 + lr) * K + lk;
    const float* Aip = AIm + (size_t)(n0 + lr) * K + lk;
    const float* Wrp = WRe + (size_t)(m0 + lr) * K + lk;
    const float* Wip = WIm + (size_t)(m0 + lr) * K + lk;
    float acc[4][4] = {};
    for (int k0 = 0; k0 < K; k0 += 16) {
        float4 ar = *(const float4*)(Arp + k0);
        float4 ai = *(const float4*)(Aip + k0);
        float4 wr = *(const float4*)(Wrp + k0);
        float4 wi = *(const float4*)(Wip + k0);
        __syncthreads();
        Ar[(lk+0)*68+lr]=ar.x; Ar[(lk+1)*68+lr]=ar.y; Ar[(lk+2)*68+lr]=ar.z; Ar[(lk+3)*68+lr]=ar.w;
        Ai[(lk+0)*68+lr]=ai.x; Ai[(lk+1)*68+lr]=ai.y; Ai[(lk+2)*68+lr]=ai.z; Ai[(lk+3)*68+lr]=ai.w;
        Wr[(lk+0)*68+lr]=wr.x; Wr[(lk+1)*68+lr]=wr.y; Wr[(lk+2)*68+lr]=wr.z; Wr[(lk+3)*68+lr]=wr.w;
        Wi[(lk+0)*68+lr]=wi.x; Wi[(lk+1)*68+lr]=wi.y; Wi[(lk+2)*68+lr]=wi.z; Wi[(lk+3)*68+lr]=wi.w;
        __syncthreads();
        #pragma unroll
        for (int kk = 0; kk < 16; kk++) {
            float4 arv = *(const float4*)&Ar[kk*68 + (ty<<2)];
            float4 aiv = *(const float4*)&Ai[kk*68 + (ty<<2)];
            float4 wrv = *(const float4*)&Wr[kk*68 + (tx<<2)];
            float4 wiv = *(const float4*)&Wi[kk*68 + (tx<<2)];
            float arr[4] = {arv.x, arv.y, arv.z, arv.w};
            float aii[4] = {-aiv.x, -aiv.y, -aiv.z, -aiv.w};
            float wr4[4] = {wrv.x, wrv.y, wrv.z, wrv.w};
            float wi4[4] = {wiv.x, wiv.y, wiv.z, wiv.w};
            #pragma unroll
            for (int i = 0; i < 4; i++)
                #pragma unroll
                for (int j = 0; j < 4; j++) {
                    acc[i][j] = fmaf(arr[i], wr4[j], acc[i][j]);
                    acc[i][j] = fmaf(aii[i], wi4[j], acc[i][j]);
                }
        }
    }
    #pragma unroll
    for (int i = 0; i < 4; i++) {
        size_t o = (size_t)(n0 + (ty<<2) + i) * M + m0 + (tx<<2);
        *(float4*)(O + o) = make_float4(acc[i][0], acc[i][1], acc[i][2], acc[i][3]);
    }
}

// ---------------- GEMM 3/4: out = A @ W^T + bias, optional exact GELU ----------------
__global__ __launch_bounds__(256) void gemm_bias(
    const float* __restrict__ A, const float* __restrict__ W,
    const float* __restrict__ bias, float* __restrict__ O,
    int M, int K, int do_gelu)
{
    __shared__ __align__(16) float As[16*68], Ws[16*68];
    const int tid = threadIdx.x;
    const int tx = tid & 15, ty = tid >> 4;
    const int n0 = blockIdx.y << 6, m0 = blockIdx.x << 6;
    const int lr = tid >> 2;
    const int lk = (tid & 3) << 2;
    const float* Ap = A + (size_t)(n0 + lr) * K + lk;
    const float* Wp = W + (size_t)(m0 + lr) * K + lk;
    float acc[4][4] = {};
    for (int k0 = 0; k0 < K; k0 += 16) {
        float4 a = *(const float4*)(Ap + k0);
        float4 w = *(const float4*)(Wp + k0);
        __syncthreads();
        As[(lk+0)*68+lr]=a.x; As[(lk+1)*68+lr]=a.y; As[(lk+2)*68+lr]=a.z; As[(lk+3)*68+lr]=a.w;
        Ws[(lk+0)*68+lr]=w.x; Ws[(lk+1)*68+lr]=w.y; Ws[(lk+2)*68+lr]=w.z; Ws[(lk+3)*68+lr]=w.w;
        __syncthreads();
        #pragma unroll
        for (int kk = 0; kk < 16; kk++) {
            float4 av = *(const float4*)&As[kk*68 + (ty<<2)];
            float4 wv = *(const float4*)&Ws[kk*68 + (tx<<2)];
            float avv[4] = {av.x, av.y, av.z, av.w};
            float wvv[4] = {wv.x, wv.y, wv.z, wv.w};
            #pragma unroll
            for (int i = 0; i < 4; i++)
                #pragma unroll
                for (int j = 0; j < 4; j++)
                    acc[i][j] = fmaf(avv[i], wvv[j], acc[i][j]);
        }
    }
    float bv[4];
    #pragma unroll
    for (int j = 0; j < 4; j++) bv[j] = bias[m0 + (tx<<2) + j];
    #pragma unroll
    for (int i = 0; i < 4; i++) {
        float v[4];
        #pragma unroll
        for (int j = 0; j < 4; j++) {
            v[j] = acc[i][j] + bv[j];
            if (do_gelu) v[j] = v[j] * normcdff(v[j]);   // exact GELU: x * Phi(x)
        }
        size_t o = (size_t)(n0 + (ty<<2) + i) * M + m0 + (tx<<2);
        *(float4*)(O + o) = make_float4(v[0], v[1], v[2], v[3]);
    }
}

// ---------------- chunked complex scan: state_s = lam*state_{s-1} + x_s ----------------
__device__ __forceinline__ void lam_of(const float* nul, const float* thl, int u,
                                       float& lre, float& lim)
{
    float r   = expf(-expf(nul[u]));
    float ang = expf(thl[u]);
    lre = r * cosf(ang);
    lim = r * sinf(ang);
}

__global__ void scan_pass1(const float* __restrict__ nul, const float* __restrict__ thl,
                           float* __restrict__ tre, float* __restrict__ tim,
                           float2* __restrict__ carry)
{
    int t = blockIdx.x * blockDim.x + threadIdx.x;   // BB*NCHUNK*HH threads
    int u = t & (HH - 1);
    int rest = t >> 10;
    int c = rest & (NCHUNK - 1);
    int b = rest >> 5;
    float lre, lim; lam_of(nul, thl, u, lre, lim);
    size_t base = ((size_t)b * SS + (size_t)c * CLEN) * HH + u;
    float sre = 0.f, sim = 0.f;
    #pragma unroll 4
    for (int i = 0; i < CLEN; i++) {
        size_t ix = base + (size_t)i * HH;
        float xr = tre[ix], xi = tim[ix];
        float nr = fmaf(lre, sre, fmaf(-lim, sim, xr));
        float ni = fmaf(lre, sim, fmaf( lim, sre, xi));
        sre = nr; sim = ni;
        tre[ix] = sre; tim[ix] = sim;
    }
    carry[(b * NCHUNK + c) * HH + u] = make_float2(sre, sim);
}

__global__ void scan_pass2(const float* __restrict__ nul, const float* __restrict__ thl,
                           float2* __restrict__ carry)
{
    int t = blockIdx.x * blockDim.x + threadIdx.x;   // BB*HH threads
    int u = t & (HH - 1);
    int b = t >> 10;
    float lre, lim; lam_of(nul, thl, u, lre, lim);
    float pr = 1.f, pi = 0.f;                        // lam^CLEN
    #pragma unroll
    for (int i = 0; i < CLEN; i++) {
        float nr = pr * lre - pi * lim;
        float ni = pr * lim + pi * lre;
        pr = nr; pi = ni;
    }
    float cre = 0.f, cim = 0.f;                      // exclusive chunk carry
    for (int c = 0; c < NCHUNK; c++) {
        int ix = (b * NCHUNK + c) * HH + u;
        float2 f = carry[ix];
        carry[ix] = make_float2(cre, cim);
        float nr = fmaf(pr, cre, fmaf(-pi, cim, f.x));
        float ni = fmaf(pr, cim, fmaf( pi, cre, f.y));
        cre = nr; cim = ni;
    }
}

__global__ void scan_pass3(const float* __restrict__ nul, const float* __restrict__ thl,
                           float* __restrict__ tre, float* __restrict__ tim,
                           const float2* __restrict__ carry)
{
    int t = blockIdx.x * blockDim.x + threadIdx.x;
    int u = t & (HH - 1);
    int rest = t >> 10;
    int c = rest & (NCHUNK - 1);
    int b = rest >> 5;
    float2 cc = carry[(b * NCHUNK + c) * HH + u];
    if (cc.x == 0.f && cc.y == 0.f) return;          // chunk 0 (and dead chains)
    float lre, lim; lam_of(nul, thl, u, lre, lim);
    size_t base = ((size_t)b * SS + (size_t)c * CLEN) * HH + u;
    float pr = lre, pi = lim;                         // lam^(i+1)
    #pragma unroll 4
    for (int i = 0; i < CLEN; i++) {
        size_t ix = base + (size_t)i * HH;
        float ar = fmaf(pr, cc.x, fmaf(-pi, cc.y, tre[ix]));
        float ai = fmaf(pr, cc.y, fmaf( pi, cc.x, tim[ix]));
        tre[ix] = ar; tim[ix] = ai;
        float nr = pr * lre - pi * lim;
        float ni = pr * lim + pi * lre;
        pr = nr; pi = ni;
    }
}

// ---------------- fused residual + RMS-LN (+ optional D*h term) ----------------
// z = h*(1+D) + y   (D==null -> z = h + y);  out = z * rsqrt(mean(z^2)+1e-12) + bias
__global__ void ln_kernel(const float* __restrict__ h, const float* __restrict__ y,
                          const float* __restrict__ Dl, const float* __restrict__ bias,
                          float* __restrict__ out)
{
    int n = blockIdx.x;
    int t = threadIdx.x;                 // 256 threads, 4 elems each
    size_t idx = (size_t)n * HH + (t << 2);
    float4 hv = *(const float4*)(h + idx);
    float4 yv = *(const float4*)(y + idx);
    float4 z;
    if (Dl) {
        float4 dv = *(const float4*)(Dl + (t << 2));
        z.x = fmaf(hv.x, 1.f + dv.x, yv.x);
        z.y = fmaf(hv.y, 1.f + dv.y, yv.y);
        z.z = fmaf(hv.z, 1.f + dv.z, yv.z);
        z.w = fmaf(hv.w, 1.f + dv.w, yv.w);
    } else {
        z.x = hv.x + yv.x; z.y = hv.y + yv.y; z.z = hv.z + yv.z; z.w = hv.w + yv.w;
    }
    float s = z.x*z.x + z.y*z.y + z.z*z.z + z.w*z.w;
    #pragma unroll
    for (int o = 16; o; o >>= 1) s += __shfl_xor_sync(0xffffffffu, s, o);
    __shared__ float red[8];
    if ((t & 31) == 0) red[t >> 5] = s;
    __syncthreads();
    float tot = red[0]+red[1]+red[2]+red[3]+red[4]+red[5]+red[6]+red[7];
    float inv = rsqrtf(tot * (1.f / (float)HH) + 1e-12f);
    float4 bv = *(const float4*)(bias + (t << 2));
    float4 o4 = make_float4(fmaf(z.x, inv, bv.x), fmaf(z.y, inv, bv.y),
                            fmaf(z.z, inv, bv.z), fmaf(z.w, inv, bv.w));
    *(float4*)(out + idx) = o4;
}

// ---------------- launch ----------------
extern "C" void kernel_launch(void* const* d_in, const int* in_sizes, int n_in,
                              void* d_out, int out_size)
{
    const int*   ids = (const int*)  d_in[0];
    const float* we  = (const float*)d_in[1];
    const float* pe  = (const float*)d_in[2];
    const float* nu  = (const float*)d_in[3];
    const float* th  = (const float*)d_in[4];
    const float* Bre = (const float*)d_in[5];
    const float* Bim = (const float*)d_in[6];
    const float* Cre = (const float*)d_in[7];
    const float* Cim = (const float*)d_in[8];
    const float* Dp  = (const float*)d_in[9];
    const float* rnb = (const float*)d_in[10];
    const float* w1  = (const float*)d_in[11];
    const float* b1  = (const float*)d_in[12];
    const float* w2  = (const float*)d_in[13];
    const float* b2  = (const float*)d_in[14];
    const float* fnb = (const float*)d_in[15];
    float* out = (float*)d_out;

    float *ph, *ptre, *ptim, *py, *pf; float2* pc;
    cudaGetSymbolAddress((void**)&ph,   g_h);
    cudaGetSymbolAddress((void**)&ptre, g_tre);
    cudaGetSymbolAddress((void**)&ptim, g_tim);
    cudaGetSymbolAddress((void**)&py,   g_y);
    cudaGetSymbolAddress((void**)&pf,   g_f);
    cudaGetSymbolAddress((void**)&pc,   g_carry);

    embed_kernel<<<(size_t)NN*HH/4/256, 256>>>(ids, we, pe, ph);

    for (int l = 0; l < LL; l++) {
        const float* nul = nu + l*HH;
        const float* thl = th + l*HH;

        gemm_bu<<<dim3(HH/64, NN/64), 256>>>(ph, Bre + (size_t)l*HH*HH, Bim + (size_t)l*HH*HH,
                                             nul, ptre, ptim, HH, HH);
        scan_pass1<<<BB*NCHUNK*HH/256, 256>>>(nul, thl, ptre, ptim, pc);
        scan_pass2<<<BB*HH/256, 256>>>(nul, thl, pc);
        scan_pass3<<<BB*NCHUNK*HH/256, 256>>>(nul, thl, ptre, ptim, pc);
        gemm_y<<<dim3(HH/64, NN/64), 256>>>(ptre, ptim, Cre + (size_t)l*HH*HH, Cim + (size_t)l*HH*HH,
                                            py, HH, HH);
        ln_kernel<<<NN, 256>>>(ph, py, Dp + l*HH, rnb + l*HH, ph);

        gemm_bias<<<dim3(FF/64, NN/64), 256>>>(ph, w1 + (size_t)l*FF*HH, b1 + l*FF, pf, FF, HH, 1);
        gemm_bias<<<dim3(HH/64, NN/64), 256>>>(pf, w2 + (size_t)l*HH*FF, b2 + l*HH, py, HH, FF, 0);

        float* lnout = (l == LL-1) ? out : ph;
        ln_kernel<<<NN, 256>>>(ph, py, nullptr, fnb + l*HH, lnout);
    }
}

// round 3
// speedup vs baseline: 1.0003x; 1.0003x over previous
#include <cuda_runtime.h>

// Problem dims (fixed by the dataset)
#define BB 4
#define SS 2048
#define HH 1024
#define LL 4
#define FF 4096
#define NN (BB*SS)          // 8192 token rows
#define NCHUNK 32
#define CLEN (SS/NCHUNK)    // 64

// ---------------- scratch (no allocations allowed) ----------------
__device__ float g_h  [(size_t)NN*HH];
__device__ float g_tre[(size_t)NN*HH];
__device__ float g_tim[(size_t)NN*HH];
__device__ float g_y  [(size_t)NN*HH];
__device__ float g_f  [(size_t)NN*FF];
__device__ float2 g_carry[BB*NCHUNK*HH];

// ---------------- embedding ----------------
__global__ void embed_kernel(const int* __restrict__ ids, const float* __restrict__ we,
                             const float* __restrict__ pe, float* __restrict__ out)
{
    int e = blockIdx.x * blockDim.x + threadIdx.x;   // one float4 per thread
    int n  = e >> 8;                                  // HH/4 = 256 quads per row
    int hq = (e & 255) << 2;
    int s  = n & (SS - 1);
    int id = ids[n];
    float4 w = *(const float4*)(we + (size_t)id * HH + hq);
    float4 p = *(const float4*)(pe + (size_t)s  * HH + hq);
    *(float4*)(out + (size_t)n * HH + hq) =
        make_float4(w.x + p.x, w.y + p.y, w.z + p.z, w.w + p.w);
}

// ---------------- GEMM 1: Bu_re/Bu_im = (h @ B^T) * gamma ----------------
// A[N,K] row-major, W[M,K] row-major (NT). dual output with shared A tile.
__global__ __launch_bounds__(256) void gemm_bu(
    const float* __restrict__ A, const float* __restrict__ WRe, const float* __restrict__ WIm,
    const float* __restrict__ nul,
    float* __restrict__ ORe, float* __restrict__ OIm, int M, int K)
{
    __shared__ __align__(16) float As[16*68], Wr[16*68], Wi[16*68];
    const int tid = threadIdx.x;
    const int tx = tid & 15, ty = tid >> 4;
    const int n0 = blockIdx.y << 6, m0 = blockIdx.x << 6;
    const int lr = tid >> 2;
    const int lk = (tid & 3) << 2;
    const float* Ap  = A   + (size_t)(n0 + lr) * K + lk;
    const float* Wrp = WRe + (size_t)(m0 + lr) * K + lk;
    const float* Wip = WIm + (size_t)(m0 + lr) * K + lk;
    float aR[4][4] = {}, aI[4][4] = {};
    for (int k0 = 0; k0 < K; k0 += 16) {
        float4 a  = *(const float4*)(Ap  + k0);
        float4 wr = *(const float4*)(Wrp + k0);
        float4 wi = *(const float4*)(Wip + k0);
        __syncthreads();
        As[(lk+0)*68+lr]=a.x;  As[(lk+1)*68+lr]=a.y;  As[(lk+2)*68+lr]=a.z;  As[(lk+3)*68+lr]=a.w;
        Wr[(lk+0)*68+lr]=wr.x; Wr[(lk+1)*68+lr]=wr.y; Wr[(lk+2)*68+lr]=wr.z; Wr[(lk+3)*68+lr]=wr.w;
        Wi[(lk+0)*68+lr]=wi.x; Wi[(lk+1)*68+lr]=wi.y; Wi[(lk+2)*68+lr]=wi.z; Wi[(lk+3)*68+lr]=wi.w;
        __syncthreads();
        #pragma unroll
        for (int kk = 0; kk < 16; kk++) {
            float4 av  = *(const float4*)&As[kk*68 + (ty<<2)];
            float4 wrv = *(const float4*)&Wr[kk*68 + (tx<<2)];
            float4 wiv = *(const float4*)&Wi[kk*68 + (tx<<2)];
            float avv[4] = {av.x, av.y, av.z, av.w};
            float wr4[4] = {wrv.x, wrv.y, wrv.z, wrv.w};
            float wi4[4] = {wiv.x, wiv.y, wiv.z, wiv.w};
            #pragma unroll
            for (int i = 0; i < 4; i++)
                #pragma unroll
                for (int j = 0; j < 4; j++) {
                    aR[i][j] = fmaf(avv[i], wr4[j], aR[i][j]);
                    aI[i][j] = fmaf(avv[i], wi4[j], aI[i][j]);
                }
        }
    }
    float gma[4];
    #pragma unroll
    for (int j = 0; j < 4; j++) {
        int u = m0 + (tx<<2) + j;
        gma[j] = sqrtf(fmaxf(1.f - expf(-2.f * expf(nul[u])), 0.f));
    }
    #pragma unroll
    for (int i = 0; i < 4; i++) {
        size_t o = (size_t)(n0 + (ty<<2) + i) * M + m0 + (tx<<2);
        *(float4*)(ORe + o) = make_float4(aR[i][0]*gma[0], aR[i][1]*gma[1], aR[i][2]*gma[2], aR[i][3]*gma[3]);
        *(float4*)(OIm + o) = make_float4(aI[i][0]*gma[0], aI[i][1]*gma[1], aI[i][2]*gma[2], aI[i][3]*gma[3]);
    }
}

// ---------------- GEMM 2: y = re @ C_re^T - im @ C_im^T ----------------
__global__ __launch_bounds__(256) void gemm_y(
    const float* __restrict__ ARe, const float* __restrict__ AIm,
    const float* __restrict__ WRe, const float* __restrict__ WIm,
    float* __restrict__ O, int M, int K)
{
    __shared__ __align__(16) float Ar[16*68], Ai[16*68], Wr[16*68], Wi[16*68];
    const int tid = threadIdx.x;
    const int tx = tid & 15, ty = tid >> 4;
    const int n0 = blockIdx.y << 6, m0 = blockIdx.x << 6;
    const int lr = tid >> 2;
    const int lk = (tid & 3) << 2;
    const float* Arp = ARe + (size_t)(n0 + lr) * K + lk;
    const float* Aip = AIm + (size_t)(n0 + lr) * K + lk;
    const float* Wrp = WRe + (size_t)(m0 + lr) * K + lk;
    const float* Wip = WIm + (size_t)(m0 + lr) * K + lk;
    float acc[4][4] = {};
    for (int k0 = 0; k0 < K; k0 += 16) {
        float4 ar = *(const float4*)(Arp + k0);
        float4 ai = *(const float4*)(Aip + k0);
        float4 wr = *(const float4*)(Wrp + k0);
        float4 wi = *(const float4*)(Wip + k0);
        __syncthreads();
        Ar[(lk+0)*68+lr]=ar.x; Ar[(lk+1)*68+lr]=ar.y; Ar[(lk+2)*68+lr]=ar.z; Ar[(lk+3)*68+lr]=ar.w;
        Ai[(lk+0)*68+lr]=ai.x; Ai[(lk+1)*68+lr]=ai.y; Ai[(lk+2)*68+lr]=ai.z; Ai[(lk+3)*68+lr]=ai.w;
        Wr[(lk+0)*68+lr]=wr.x; Wr[(lk+1)*68+lr]=wr.y; Wr[(lk+2)*68+lr]=wr.z; Wr[(lk+3)*68+lr]=wr.w;
        Wi[(lk+0)*68+lr]=wi.x; Wi[(lk+1)*68+lr]=wi.y; Wi[(lk+2)*68+lr]=wi.z; Wi[(lk+3)*68+lr]=wi.w;
        __syncthreads();
        #pragma unroll
        for (int kk = 0; kk < 16; kk++) {
            float4 arv = *(const float4*)&Ar[kk*68 + (ty<<2)];
            float4 aiv = *(const float4*)&Ai[kk*68 + (ty<<2)];
            float4 wrv = *(const float4*)&Wr[kk*68 + (tx<<2)];
            float4 wiv = *(const float4*)&Wi[kk*68 + (tx<<2)];
            float arr[4] = {arv.x, arv.y, arv.z, arv.w};
            float aii[4] = {-aiv.x, -aiv.y, -aiv.z, -aiv.w};
            float wr4[4] = {wrv.x, wrv.y, wrv.z, wrv.w};
            float wi4[4] = {wiv.x, wiv.y, wiv.z, wiv.w};
            #pragma unroll
            for (int i = 0; i < 4; i++)
                #pragma unroll
                for (int j = 0; j < 4; j++) {
                    acc[i][j] = fmaf(arr[i], wr4[j], acc[i][j]);
                    acc[i][j] = fmaf(aii[i], wi4[j], acc[i][j]);
                }
        }
    }
    #pragma unroll
    for (int i = 0; i < 4; i++) {
        size_t o = (size_t)(n0 + (ty<<2) + i) * M + m0 + (tx<<2);
        *(float4*)(O + o) = make_float4(acc[i][0], acc[i][1], acc[i][2], acc[i][3]);
    }
}

// ---------------- GEMM 3/4: out = A @ W^T + bias, optional exact GELU ----------------
__global__ __launch_bounds__(256) void gemm_bias(
    const float* __restrict__ A, const float* __restrict__ W,
    const float* __restrict__ bias, float* __restrict__ O,
    int M, int K, int do_gelu)
{
    __shared__ __align__(16) float As[16*68], Ws[16*68];
    const int tid = threadIdx.x;
    const int tx = tid & 15, ty = tid >> 4;
    const int n0 = blockIdx.y << 6, m0 = blockIdx.x << 6;
    const int lr = tid >> 2;
    const int lk = (tid & 3) << 2;
    const float* Ap = A + (size_t)(n0 + lr) * K + lk;
    const float* Wp = W + (size_t)(m0 + lr) * K + lk;
    float acc[4][4] = {};
    for (int k0 = 0; k0 < K; k0 += 16) {
        float4 a = *(const float4*)(Ap + k0);
        float4 w = *(const float4*)(Wp + k0);
        __syncthreads();
        As[(lk+0)*68+lr]=a.x; As[(lk+1)*68+lr]=a.y; As[(lk+2)*68+lr]=a.z; As[(lk+3)*68+lr]=a.w;
        Ws[(lk+0)*68+lr]=w.x; Ws[(lk+1)*68+lr]=w.y; Ws[(lk+2)*68+lr]=w.z; Ws[(lk+3)*68+lr]=w.w;
        __syncthreads();
        #pragma unroll
        for (int kk = 0; kk < 16; kk++) {
            float4 av = *(const float4*)&As[kk*68 + (ty<<2)];
            float4 wv = *(const float4*)&Ws[kk*68 + (tx<<2)];
            float avv[4] = {av.x, av.y, av.z, av.w};
            float wvv[4] = {wv.x, wv.y, wv.z, wv.w};
            #pragma unroll
            for (int i = 0; i < 4; i++)
                #pragma unroll
                for (int j = 0; j < 4; j++)
                    acc[i][j] = fmaf(avv[i], wvv[j], acc[i][j]);
        }
    }
    float bv[4];
    #pragma unroll
    for (int j = 0; j < 4; j++) bv[j] = bias[m0 + (tx<<2) + j];
    #pragma unroll
    for (int i = 0; i < 4; i++) {
        float v[4];
        #pragma unroll
        for (int j = 0; j < 4; j++) {
            v[j] = acc[i][j] + bv[j];
            if (do_gelu) v[j] = v[j] * normcdff(v[j]);   // exact GELU: x * Phi(x)
        }
        size_t o = (size_t)(n0 + (ty<<2) + i) * M + m0 + (tx<<2);
        *(float4*)(O + o) = make_float4(v[0], v[1], v[2], v[3]);
    }
}

// ---------------- chunked complex scan: state_s = lam*state_{s-1} + x_s ----------------
__device__ __forceinline__ void lam_of(const float* nul, const float* thl, int u,
                                       float& lre, float& lim)
{
    float r   = expf(-expf(nul[u]));
    float ang = expf(thl[u]);
    lre = r * cosf(ang);
    lim = r * sinf(ang);
}

__global__ void scan_pass1(const float* __restrict__ nul, const float* __restrict__ thl,
                           float* __restrict__ tre, float* __restrict__ tim,
                           float2* __restrict__ carry)
{
    int t = blockIdx.x * blockDim.x + threadIdx.x;   // BB*NCHUNK*HH threads
    int u = t & (HH - 1);
    int rest = t >> 10;
    int c = rest & (NCHUNK - 1);
    int b = rest >> 5;
    float lre, lim; lam_of(nul, thl, u, lre, lim);
    size_t base = ((size_t)b * SS + (size_t)c * CLEN) * HH + u;
    float sre = 0.f, sim = 0.f;
    #pragma unroll 4
    for (int i = 0; i < CLEN; i++) {
        size_t ix = base + (size_t)i * HH;
        float xr = tre[ix], xi = tim[ix];
        float nr = fmaf(lre, sre, fmaf(-lim, sim, xr));
        float ni = fmaf(lre, sim, fmaf( lim, sre, xi));
        sre = nr; sim = ni;
        tre[ix] = sre; tim[ix] = sim;
    }
    carry[(b * NCHUNK + c) * HH + u] = make_float2(sre, sim);
}

__global__ void scan_pass2(const float* __restrict__ nul, const float* __restrict__ thl,
                           float2* __restrict__ carry)
{
    int t = blockIdx.x * blockDim.x + threadIdx.x;   // BB*HH threads
    int u = t & (HH - 1);
    int b = t >> 10;
    float lre, lim; lam_of(nul, thl, u, lre, lim);
    float pr = 1.f, pi = 0.f;                        // lam^CLEN
    #pragma unroll
    for (int i = 0; i < CLEN; i++) {
        float nr = pr * lre - pi * lim;
        float ni = pr * lim + pi * lre;
        pr = nr; pi = ni;
    }
    float cre = 0.f, cim = 0.f;                      // exclusive chunk carry
    for (int c = 0; c < NCHUNK; c++) {
        int ix = (b * NCHUNK + c) * HH + u;
        float2 f = carry[ix];
        carry[ix] = make_float2(cre, cim);
        float nr = fmaf(pr, cre, fmaf(-pi, cim, f.x));
        float ni = fmaf(pr, cim, fmaf( pi, cre, f.y));
        cre = nr; cim = ni;
    }
}

__global__ void scan_pass3(const float* __restrict__ nul, const float* __restrict__ thl,
                           float* __restrict__ tre, float* __restrict__ tim,
                           const float2* __restrict__ carry)
{
    int t = blockIdx.x * blockDim.x + threadIdx.x;
    int u = t & (HH - 1);
    int rest = t >> 10;
    int c = rest & (NCHUNK - 1);
    int b = rest >> 5;
    float2 cc = carry[(b * NCHUNK + c) * HH + u];
    if (cc.x == 0.f && cc.y == 0.f) return;          // chunk 0 (and dead chains)
    float lre, lim; lam_of(nul, thl, u, lre, lim);
    size_t base = ((size_t)b * SS + (size_t)c * CLEN) * HH + u;
    float pr = lre, pi = lim;                         // lam^(i+1)
    #pragma unroll 4
    for (int i = 0; i < CLEN; i++) {
        size_t ix = base + (size_t)i * HH;
        float ar = fmaf(pr, cc.x, fmaf(-pi, cc.y, tre[ix]));
        float ai = fmaf(pr, cc.y, fmaf( pi, cc.x, tim[ix]));
        tre[ix] = ar; tim[ix] = ai;
        float nr = pr * lre - pi * lim;
        float ni = pr * lim + pi * lre;
        pr = nr; pi = ni;
    }
}

// ---------------- fused residual + RMS-LN (+ optional D*h term) ----------------
// z = h*(1+D) + y   (D==null -> z = h + y);  out = z * rsqrt(mean(z^2)+1e-12) + bias
__global__ void ln_kernel(const float* __restrict__ h, const float* __restrict__ y,
                          const float* __restrict__ Dl, const float* __restrict__ bias,
                          float* __restrict__ out)
{
    int n = blockIdx.x;
    int t = threadIdx.x;                 // 256 threads, 4 elems each
    size_t idx = (size_t)n * HH + (t << 2);
    float4 hv = *(const float4*)(h + idx);
    float4 yv = *(const float4*)(y + idx);
    float4 z;
    if (Dl) {
        float4 dv = *(const float4*)(Dl + (t << 2));
        z.x = fmaf(hv.x, 1.f + dv.x, yv.x);
        z.y = fmaf(hv.y, 1.f + dv.y, yv.y);
        z.z = fmaf(hv.z, 1.f + dv.z, yv.z);
        z.w = fmaf(hv.w, 1.f + dv.w, yv.w);
    } else {
        z.x = hv.x + yv.x; z.y = hv.y + yv.y; z.z = hv.z + yv.z; z.w = hv.w + yv.w;
    }
    float s = z.x*z.x + z.y*z.y + z.z*z.z + z.w*z.w;
    #pragma unroll
    for (int o = 16; o; o >>= 1) s += __shfl_xor_sync(0xffffffffu, s, o);
    __shared__ float red[8];
    if ((t & 31) == 0) red[t >> 5] = s;
    __syncthreads();
    float tot = red[0]+red[1]+red[2]+red[3]+red[4]+red[5]+red[6]+red[7];
    float inv = rsqrtf(tot * (1.f / (float)HH) + 1e-12f);
    float4 bv = *(const float4*)(bias + (t << 2));
    float4 o4 = make_float4(fmaf(z.x, inv, bv.x), fmaf(z.y, inv, bv.y),
                            fmaf(z.z, inv, bv.z), fmaf(z.w, inv, bv.w));
    *(float4*)(out + idx) = o4;
}

// ---------------- launch ----------------
extern "C" void kernel_launch(void* const* d_in, const int* in_sizes, int n_in,
                              void* d_out, int out_size)
{
    const int*   ids = (const int*)  d_in[0];
    const float* we  = (const float*)d_in[1];
    const float* pe  = (const float*)d_in[2];
    const float* nu  = (const float*)d_in[3];
    const float* th  = (const float*)d_in[4];
    const float* Bre = (const float*)d_in[5];
    const float* Bim = (const float*)d_in[6];
    const float* Cre = (const float*)d_in[7];
    const float* Cim = (const float*)d_in[8];
    const float* Dp  = (const float*)d_in[9];
    const float* rnb = (const float*)d_in[10];
    const float* w1  = (const float*)d_in[11];
    const float* b1  = (const float*)d_in[12];
    const float* w2  = (const float*)d_in[13];
    const float* b2  = (const float*)d_in[14];
    const float* fnb = (const float*)d_in[15];
    float* out = (float*)d_out;

    float *ph, *ptre, *ptim, *py, *pf; float2* pc;
    cudaGetSymbolAddress((void**)&ph,   g_h);
    cudaGetSymbolAddress((void**)&ptre, g_tre);
    cudaGetSymbolAddress((void**)&ptim, g_tim);
    cudaGetSymbolAddress((void**)&py,   g_y);
    cudaGetSymbolAddress((void**)&pf,   g_f);
    cudaGetSymbolAddress((void**)&pc,   g_carry);

    embed_kernel<<<(size_t)NN*HH/4/256, 256>>>(ids, we, pe, ph);

    for (int l = 0; l < LL; l++) {
        const float* nul = nu + l*HH;
        const float* thl = th + l*HH;

        gemm_bu<<<dim3(HH/64, NN/64), 256>>>(ph, Bre + (size_t)l*HH*HH, Bim + (size_t)l*HH*HH,
                                             nul, ptre, ptim, HH, HH);
        scan_pass1<<<BB*NCHUNK*HH/256, 256>>>(nul, thl, ptre, ptim, pc);
        scan_pass2<<<BB*HH/256, 256>>>(nul, thl, pc);
        scan_pass3<<<BB*NCHUNK*HH/256, 256>>>(nul, thl, ptre, ptim, pc);
        gemm_y<<<dim3(HH/64, NN/64), 256>>>(ptre, ptim, Cre + (size_t)l*HH*HH, Cim + (size_t)l*HH*HH,
                                            py, HH, HH);
        ln_kernel<<<NN, 256>>>(ph, py, Dp + l*HH, rnb + l*HH, ph);

        gemm_bias<<<dim3(FF/64, NN/64), 256>>>(ph, w1 + (size_t)l*FF*HH, b1 + l*FF, pf, FF, HH, 1);
        gemm_bias<<<dim3(HH/64, NN/64), 256>>>(pf, w2 + (size_t)l*HH*FF, b2 + l*HH, py, HH, FF, 0);

        float* lnout = (l == LL-1) ? out : ph;
        ln_kernel<<<NN, 256>>>(ph, py, nullptr, fnb + l*HH, lnout);
    }
}

// round 4
// speedup vs baseline: 1.0014x; 1.0011x over previous
#include <cuda_runtime.h>

// Problem dims (fixed by the dataset)
#define BB 4
#define SS 2048
#define HH 1024
#define LL 4
#define FF 4096
#define NN (BB*SS)          // 8192 token rows
#define NCHUNK 32
#define CLEN (SS/NCHUNK)    // 64

// ---------------- scratch (no allocations allowed) ----------------
__device__ float g_h  [(size_t)NN*HH];
__device__ float g_tre[(size_t)NN*HH];
__device__ float g_tim[(size_t)NN*HH];
__device__ float g_y  [(size_t)NN*HH];
__device__ float g_f  [(size_t)NN*FF];
__device__ float2 g_carry[BB*NCHUNK*HH];

// ---------------- embedding ----------------
__global__ void embed_kernel(const int* __restrict__ ids, const float* __restrict__ we,
                             const float* __restrict__ pe, float* __restrict__ out)
{
    int e = blockIdx.x * blockDim.x + threadIdx.x;   // one float4 per thread
    int n  = e >> 8;                                  // HH/4 = 256 quads per row
    int hq = (e & 255) << 2;
    int s  = n & (SS - 1);
    int id = ids[n];
    float4 w = *(const float4*)(we + (size_t)id * HH + hq);
    float4 p = *(const float4*)(pe + (size_t)s  * HH + hq);
    *(float4*)(out + (size_t)n * HH + hq) =
        make_float4(w.x + p.x, w.y + p.y, w.z + p.z, w.w + p.w);
}

// ---------------- GEMM 1: Bu_re/Bu_im = (h @ B^T) * gamma ----------------
// A[N,K] row-major, W[M,K] row-major (NT). dual output with shared A tile.
__global__ __launch_bounds__(256) void gemm_bu(
    const float* __restrict__ A, const float* __restrict__ WRe, const float* __restrict__ WIm,
    const float* __restrict__ nul,
    float* __restrict__ ORe, float* __restrict__ OIm, int M, int K)
{
    __shared__ __align__(16) float As[16*68], Wr[16*68], Wi[16*68];
    const int tid = threadIdx.x;
    const int tx = tid & 15, ty = tid >> 4;
    const int n0 = blockIdx.y << 6, m0 = blockIdx.x << 6;
    const int lr = tid >> 2;
    const int lk = (tid & 3) << 2;
    const float* Ap  = A   + (size_t)(n0 + lr) * K + lk;
    const float* Wrp = WRe + (size_t)(m0 + lr) * K + lk;
    const float* Wip = WIm + (size_t)(m0 + lr) * K + lk;
    float aR[4][4] = {}, aI[4][4] = {};
    for (int k0 = 0; k0 < K; k0 += 16) {
        float4 a  = *(const float4*)(Ap  + k0);
        float4 wr = *(const float4*)(Wrp + k0);
        float4 wi = *(const float4*)(Wip + k0);
        __syncthreads();
        As[(lk+0)*68+lr]=a.x;  As[(lk+1)*68+lr]=a.y;  As[(lk+2)*68+lr]=a.z;  As[(lk+3)*68+lr]=a.w;
        Wr[(lk+0)*68+lr]=wr.x; Wr[(lk+1)*68+lr]=wr.y; Wr[(lk+2)*68+lr]=wr.z; Wr[(lk+3)*68+lr]=wr.w;
        Wi[(lk+0)*68+lr]=wi.x; Wi[(lk+1)*68+lr]=wi.y; Wi[(lk+2)*68+lr]=wi.z; Wi[(lk+3)*68+lr]=wi.w;
        __syncthreads();
        #pragma unroll
        for (int kk = 0; kk < 16; kk++) {
            float4 av  = *(const float4*)&As[kk*68 + (ty<<2)];
            float4 wrv = *(const float4*)&Wr[kk*68 + (tx<<2)];
            float4 wiv = *(const float4*)&Wi[kk*68 + (tx<<2)];
            float avv[4] = {av.x, av.y, av.z, av.w};
            float wr4[4] = {wrv.x, wrv.y, wrv.z, wrv.w};
            float wi4[4] = {wiv.x, wiv.y, wiv.z, wiv.w};
            #pragma unroll
            for (int i = 0; i < 4; i++)
                #pragma unroll
                for (int j = 0; j < 4; j++) {
                    aR[i][j] = fmaf(avv[i], wr4[j], aR[i][j]);
                    aI[i][j] = fmaf(avv[i], wi4[j], aI[i][j]);
                }
        }
    }
    float gma[4];
    #pragma unroll
    for (int j = 0; j < 4; j++) {
        int u = m0 + (tx<<2) + j;
        gma[j] = sqrtf(fmaxf(1.f - expf(-2.f * expf(nul[u])), 0.f));
    }
    #pragma unroll
    for (int i = 0; i < 4; i++) {
        size_t o = (size_t)(n0 + (ty<<2) + i) * M + m0 + (tx<<2);
        *(float4*)(ORe + o) = make_float4(aR[i][0]*gma[0], aR[i][1]*gma[1], aR[i][2]*gma[2], aR[i][3]*gma[3]);
        *(float4*)(OIm + o) = make_float4(aI[i][0]*gma[0], aI[i][1]*gma[1], aI[i][2]*gma[2], aI[i][3]*gma[3]);
    }
}

// ---------------- GEMM 2: y = re @ C_re^T - im @ C_im^T ----------------
__global__ __launch_bounds__(256) void gemm_y(
    const float* __restrict__ ARe, const float* __restrict__ AIm,
    const float* __restrict__ WRe, const float* __restrict__ WIm,
    float* __restrict__ O, int M, int K)
{
    __shared__ __align__(16) float Ar[16*68], Ai[16*68], Wr[16*68], Wi[16*68];
    const int tid = threadIdx.x;
    const int tx = tid & 15, ty = tid >> 4;
    const int n0 = blockIdx.y << 6, m0 = blockIdx.x << 6;
    const int lr = tid >> 2;
    const int lk = (tid & 3) << 2;
    const float* Arp = ARe + (size_t)(n0 + lr) * K + lk;
    const float* Aip = AIm + (size_t)(n0 + lr) * K + lk;
    const float* Wrp = WRe + (size_t)(m0 + lr) * K + lk;
    const float* Wip = WIm + (size_t)(m0 + lr) * K + lk;
    float acc[4][4] = {};
    for (int k0 = 0; k0 < K; k0 += 16) {
        float4 ar = *(const float4*)(Arp + k0);
        float4 ai = *(const float4*)(Aip + k0);
        float4 wr = *(const float4*)(Wrp + k0);
        float4 wi = *(const float4*)(Wip + k0);
        __syncthreads();
        Ar[(lk+0)*68+lr]=ar.x; Ar[(lk+1)*68+lr]=ar.y; Ar[(lk+2)*68+lr]=ar.z; Ar[(lk+3)*68+lr]=ar.w;
        Ai[(lk+0)*68+lr]=ai.x; Ai[(lk+1)*68+lr]=ai.y; Ai[(lk+2)*68+lr]=ai.z; Ai[(lk+3)*68+lr]=ai.w;
        Wr[(lk+0)*68+lr]=wr.x; Wr[(lk+1)*68+lr]=wr.y; Wr[(lk+2)*68+lr]=wr.z; Wr[(lk+3)*68+lr]=wr.w;
        Wi[(lk+0)*68+lr]=wi.x; Wi[(lk+1)*68+lr]=wi.y; Wi[(lk+2)*68+lr]=wi.z; Wi[(lk+3)*68+lr]=wi.w;
        __syncthreads();
        #pragma unroll
        for (int kk = 0; kk < 16; kk++) {
            float4 arv = *(const float4*)&Ar[kk*68 + (ty<<2)];
            float4 aiv = *(const float4*)&Ai[kk*68 + (ty<<2)];
            float4 wrv = *(const float4*)&Wr[kk*68 + (tx<<2)];
            float4 wiv = *(const float4*)&Wi[kk*68 + (tx<<2)];
            float arr[4] = {arv.x, arv.y, arv.z, arv.w};
            float aii[4] = {-aiv.x, -aiv.y, -aiv.z, -aiv.w};
            float wr4[4] = {wrv.x, wrv.y, wrv.z, wrv.w};
            float wi4[4] = {wiv.x, wiv.y, wiv.z, wiv.w};
            #pragma unroll
            for (int i = 0; i < 4; i++)
                #pragma unroll
                for (int j = 0; j < 4; j++) {
                    acc[i][j] = fmaf(arr[i], wr4[j], acc[i][j]);
                    acc[i][j] = fmaf(aii[i], wi4[j], acc[i][j]);
                }
        }
    }
    #pragma unroll
    for (int i = 0; i < 4; i++) {
        size_t o = (size_t)(n0 + (ty<<2) + i) * M + m0 + (tx<<2);
        *(float4*)(O + o) = make_float4(acc[i][0], acc[i][1], acc[i][2], acc[i][3]);
    }
}

// ---------------- GEMM 3/4: out = A @ W^T + bias, optional exact GELU ----------------
__global__ __launch_bounds__(256) void gemm_bias(
    const float* __restrict__ A, const float* __restrict__ W,
    const float* __restrict__ bias, float* __restrict__ O,
    int M, int K, int do_gelu)
{
    __shared__ __align__(16) float As[16*68], Ws[16*68];
    const int tid = threadIdx.x;
    const int tx = tid & 15, ty = tid >> 4;
    const int n0 = blockIdx.y << 6, m0 = blockIdx.x << 6;
    const int lr = tid >> 2;
    const int lk = (tid & 3) << 2;
    const float* Ap = A + (size_t)(n0 + lr) * K + lk;
    const float* Wp = W + (size_t)(m0 + lr) * K + lk;
    float acc[4][4] = {};
    for (int k0 = 0; k0 < K; k0 += 16) {
        float4 a = *(const float4*)(Ap + k0);
        float4 w = *(const float4*)(Wp + k0);
        __syncthreads();
        As[(lk+0)*68+lr]=a.x; As[(lk+1)*68+lr]=a.y; As[(lk+2)*68+lr]=a.z; As[(lk+3)*68+lr]=a.w;
        Ws[(lk+0)*68+lr]=w.x; Ws[(lk+1)*68+lr]=w.y; Ws[(lk+2)*68+lr]=w.z; Ws[(lk+3)*68+lr]=w.w;
        __syncthreads();
        #pragma unroll
        for (int kk = 0; kk < 16; kk++) {
            float4 av = *(const float4*)&As[kk*68 + (ty<<2)];
            float4 wv = *(const float4*)&Ws[kk*68 + (tx<<2)];
            float avv[4] = {av.x, av.y, av.z, av.w};
            float wvv[4] = {wv.x, wv.y, wv.z, wv.w};
            #pragma unroll
            for (int i = 0; i < 4; i++)
                #pragma unroll
                for (int j = 0; j < 4; j++)
                    acc[i][j] = fmaf(avv[i], wvv[j], acc[i][j]);
        }
    }
    float bv[4];
    #pragma unroll
    for (int j = 0; j < 4; j++) bv[j] = bias[m0 + (tx<<2) + j];
    #pragma unroll
    for (int i = 0; i < 4; i++) {
        float v[4];
        #pragma unroll
        for (int j = 0; j < 4; j++) {
            v[j] = acc[i][j] + bv[j];
            if (do_gelu) v[j] = v[j] * normcdff(v[j]);   // exact GELU: x * Phi(x)
        }
        size_t o = (size_t)(n0 + (ty<<2) + i) * M + m0 + (tx<<2);
        *(float4*)(O + o) = make_float4(v[0], v[1], v[2], v[3]);
    }
}

// ---------------- chunked complex scan: state_s = lam*state_{s-1} + x_s ----------------
__device__ __forceinline__ void lam_of(const float* nul, const float* thl, int u,
                                       float& lre, float& lim)
{
    float r   = expf(-expf(nul[u]));
    float ang = expf(thl[u]);
    lre = r * cosf(ang);
    lim = r * sinf(ang);
}

__global__ void scan_pass1(const float* __restrict__ nul, const float* __restrict__ thl,
                           float* __restrict__ tre, float* __restrict__ tim,
                           float2* __restrict__ carry)
{
    int t = blockIdx.x * blockDim.x + threadIdx.x;   // BB*NCHUNK*HH threads
    int u = t & (HH - 1);
    int rest = t >> 10;
    int c = rest & (NCHUNK - 1);
    int b = rest >> 5;
    float lre, lim; lam_of(nul, thl, u, lre, lim);
    size_t base = ((size_t)b * SS + (size_t)c * CLEN) * HH + u;
    float sre = 0.f, sim = 0.f;
    #pragma unroll 4
    for (int i = 0; i < CLEN; i++) {
        size_t ix = base + (size_t)i * HH;
        float xr = tre[ix], xi = tim[ix];
        float nr = fmaf(lre, sre, fmaf(-lim, sim, xr));
        float ni = fmaf(lre, sim, fmaf( lim, sre, xi));
        sre = nr; sim = ni;
        tre[ix] = sre; tim[ix] = sim;
    }
    carry[(b * NCHUNK + c) * HH + u] = make_float2(sre, sim);
}

__global__ void scan_pass2(const float* __restrict__ nul, const float* __restrict__ thl,
                           float2* __restrict__ carry)
{
    int t = blockIdx.x * blockDim.x + threadIdx.x;   // BB*HH threads
    int u = t & (HH - 1);
    int b = t >> 10;
    float lre, lim; lam_of(nul, thl, u, lre, lim);
    float pr = 1.f, pi = 0.f;                        // lam^CLEN
    #pragma unroll
    for (int i = 0; i < CLEN; i++) {
        float nr = pr * lre - pi * lim;
        float ni = pr * lim + pi * lre;
        pr = nr; pi = ni;
    }
    float cre = 0.f, cim = 0.f;                      // exclusive chunk carry
    for (int c = 0; c < NCHUNK; c++) {
        int ix = (b * NCHUNK + c) * HH + u;
        float2 f = carry[ix];
        carry[ix] = make_float2(cre, cim);
        float nr = fmaf(pr, cre, fmaf(-pi, cim, f.x));
        float ni = fmaf(pr, cim, fmaf( pi, cre, f.y));
        cre = nr; cim = ni;
    }
}

__global__ void scan_pass3(const float* __restrict__ nul, const float* __restrict__ thl,
                           float* __restrict__ tre, float* __restrict__ tim,
                           const float2* __restrict__ carry)
{
    int t = blockIdx.x * blockDim.x + threadIdx.x;
    int u = t & (HH - 1);
    int rest = t >> 10;
    int c = rest & (NCHUNK - 1);
    int b = rest >> 5;
    float2 cc = carry[(b * NCHUNK + c) * HH + u];
    if (cc.x == 0.f && cc.y == 0.f) return;          // chunk 0 (and dead chains)
    float lre, lim; lam_of(nul, thl, u, lre, lim);
    size_t base = ((size_t)b * SS + (size_t)c * CLEN) * HH + u;
    float pr = lre, pi = lim;                         // lam^(i+1)
    #pragma unroll 4
    for (int i = 0; i < CLEN; i++) {
        size_t ix = base + (size_t)i * HH;
        float ar = fmaf(pr, cc.x, fmaf(-pi, cc.y, tre[ix]));
        float ai = fmaf(pr, cc.y, fmaf( pi, cc.x, tim[ix]));
        tre[ix] = ar; tim[ix] = ai;
        float nr = pr * lre - pi * lim;
        float ni = pr * lim + pi * lre;
        pr = nr; pi = ni;
    }
}

// ---------------- fused residual + RMS-LN (+ optional D*h term) ----------------
// z = h*(1+D) + y   (D==null -> z = h + y);  out = z * rsqrt(mean(z^2)+1e-12) + bias
__global__ void ln_kernel(const float* __restrict__ h, const float* __restrict__ y,
                          const float* __restrict__ Dl, const float* __restrict__ bias,
                          float* __restrict__ out)
{
    int n = blockIdx.x;
    int t = threadIdx.x;                 // 256 threads, 4 elems each
    size_t idx = (size_t)n * HH + (t << 2);
    float4 hv = *(const float4*)(h + idx);
    float4 yv = *(const float4*)(y + idx);
    float4 z;
    if (Dl) {
        float4 dv = *(const float4*)(Dl + (t << 2));
        z.x = fmaf(hv.x, 1.f + dv.x, yv.x);
        z.y = fmaf(hv.y, 1.f + dv.y, yv.y);
        z.z = fmaf(hv.z, 1.f + dv.z, yv.z);
        z.w = fmaf(hv.w, 1.f + dv.w, yv.w);
    } else {
        z.x = hv.x + yv.x; z.y = hv.y + yv.y; z.z = hv.z + yv.z; z.w = hv.w + yv.w;
    }
    float s = z.x*z.x + z.y*z.y + z.z*z.z + z.w*z.w;
    #pragma unroll
    for (int o = 16; o; o >>= 1) s += __shfl_xor_sync(0xffffffffu, s, o);
    __shared__ float red[8];
    if ((t & 31) == 0) red[t >> 5] = s;
    __syncthreads();
    float tot = red[0]+red[1]+red[2]+red[3]+red[4]+red[5]+red[6]+red[7];
    float inv = rsqrtf(tot * (1.f / (float)HH) + 1e-12f);
    float4 bv = *(const float4*)(bias + (t << 2));
    float4 o4 = make_float4(fmaf(z.x, inv, bv.x), fmaf(z.y, inv, bv.y),
                            fmaf(z.z, inv, bv.z), fmaf(z.w, inv, bv.w));
    *(float4*)(out + idx) = o4;
}

// ---------------- launch ----------------
extern "C" void kernel_launch(void* const* d_in, const int* in_sizes, int n_in,
                              void* d_out, int out_size)
{
    const int*   ids = (const int*)  d_in[0];
    const float* we  = (const float*)d_in[1];
    const float* pe  = (const float*)d_in[2];
    const float* nu  = (const float*)d_in[3];
    const float* th  = (const float*)d_in[4];
    const float* Bre = (const float*)d_in[5];
    const float* Bim = (const float*)d_in[6];
    const float* Cre = (const float*)d_in[7];
    const float* Cim = (const float*)d_in[8];
    const float* Dp  = (const float*)d_in[9];
    const float* rnb = (const float*)d_in[10];
    const float* w1  = (const float*)d_in[11];
    const float* b1  = (const float*)d_in[12];
    const float* w2  = (const float*)d_in[13];
    const float* b2  = (const float*)d_in[14];
    const float* fnb = (const float*)d_in[15];
    float* out = (float*)d_out;

    float *ph, *ptre, *ptim, *py, *pf; float2* pc;
    cudaGetSymbolAddress((void**)&ph,   g_h);
    cudaGetSymbolAddress((void**)&ptre, g_tre);
    cudaGetSymbolAddress((void**)&ptim, g_tim);
    cudaGetSymbolAddress((void**)&py,   g_y);
    cudaGetSymbolAddress((void**)&pf,   g_f);
    cudaGetSymbolAddress((void**)&pc,   g_carry);

    embed_kernel<<<(size_t)NN*HH/4/256, 256>>>(ids, we, pe, ph);

    for (int l = 0; l < LL; l++) {
        const float* nul = nu + l*HH;
        const float* thl = th + l*HH;

        gemm_bu<<<dim3(HH/64, NN/64), 256>>>(ph, Bre + (size_t)l*HH*HH, Bim + (size_t)l*HH*HH,
                                             nul, ptre, ptim, HH, HH);
        scan_pass1<<<BB*NCHUNK*HH/256, 256>>>(nul, thl, ptre, ptim, pc);
        scan_pass2<<<BB*HH/256, 256>>>(nul, thl, pc);
        scan_pass3<<<BB*NCHUNK*HH/256, 256>>>(nul, thl, ptre, ptim, pc);
        gemm_y<<<dim3(HH/64, NN/64), 256>>>(ptre, ptim, Cre + (size_t)l*HH*HH, Cim + (size_t)l*HH*HH,
                                            py, HH, HH);
        ln_kernel<<<NN, 256>>>(ph, py, Dp + l*HH, rnb + l*HH, ph);

        gemm_bias<<<dim3(FF/64, NN/64), 256>>>(ph, w1 + (size_t)l*FF*HH, b1 + l*FF, pf, FF, HH, 1);
        gemm_bias<<<dim3(HH/64, NN/64), 256>>>(pf, w2 + (size_t)l*HH*FF, b2 + l*HH, py, HH, FF, 0);

        float* lnout = (l == LL-1) ? out : ph;
        ln_kernel<<<NN, 256>>>(ph, py, nullptr, fnb + l*HH, lnout);
    }
}

// round 6
// speedup vs baseline: 2.3183x; 2.3151x over previous
#include <cuda_runtime.h>
#include <cuda_bf16.h>
#include <cstdint>

#define BB 4
#define SS 2048
#define HH 1024
#define LL 4
#define FF 4096
#define NN (BB*SS)
#define NCHUNK 32
#define CLEN (SS/NCHUNK)

// GEMM tiling: BM=128 tokens, BN=128 outputs, BK=32 bf16, 4 stages
#define PITCH 80                    // 64B data + 16B pad per 32-bf16 row
#define A_BYTES (128*PITCH)         // 10240
#define STG_BYTES (2*A_BYTES)       // 20480 (A + B)
#define NSTAGE 4
#define SMEM_SZ (NSTAGE*STG_BYTES)  // 81920

// ---------------- scratch ----------------
__device__ __align__(256) float g_h  [(size_t)NN*HH];
__device__ __align__(256) float g_tre[(size_t)NN*HH];
__device__ __align__(256) float g_tim[(size_t)NN*HH];
__device__ __align__(256) float g_y  [(size_t)NN*HH];
__device__ float2 g_carry[BB*NCHUNK*HH];
__device__ __align__(256) __nv_bfloat16 g_hs[(size_t)NN*2*HH];   // h split [hi|lo]
__device__ __align__(256) __nv_bfloat16 g_sp[(size_t)NN*4*HH];   // scan out [re_hi|re_lo|im_hi|im_lo]
__device__ __align__(256) __nv_bfloat16 g_fs[(size_t)NN*2*FF];   // gelu out [hi|lo]
__device__ __align__(256) __nv_bfloat16 g_wbu[(size_t)LL*2048*2048];
__device__ __align__(256) __nv_bfloat16 g_wy [(size_t)LL*1024*4096];
__device__ __align__(256) __nv_bfloat16 g_wf1[(size_t)LL*4096*2048];
__device__ __align__(256) __nv_bfloat16 g_wf2[(size_t)LL*1024*8192];

// ---------------- helpers ----------------
__device__ __forceinline__ uint32_t smem_u32(const void* p){
    uint32_t a;
    asm("{ .reg .u64 t; cvta.to.shared.u64 t, %1; cvt.u32.u64 %0, t; }" : "=r"(a) : "l"(p));
    return a;
}
#define CPA_COMMIT() asm volatile("cp.async.commit_group;" ::: "memory")
#define CPA_WAIT2()  asm volatile("cp.async.wait_group 2;" ::: "memory")
__device__ __forceinline__ void cpa16(uint32_t d, const void* s){
    asm volatile("cp.async.cg.shared.global [%0], [%1], 16;" :: "r"(d), "l"(s));
}
__device__ __forceinline__ void ldsm4(uint32_t& r0, uint32_t& r1, uint32_t& r2, uint32_t& r3, uint32_t a){
    asm volatile("ldmatrix.sync.aligned.m8n8.x4.shared.b16 {%0,%1,%2,%3}, [%4];"
        : "=r"(r0), "=r"(r1), "=r"(r2), "=r"(r3) : "r"(a));
}
__device__ __forceinline__ void mma16816(float* d, const uint32_t* a, const uint32_t* b){
    asm volatile("mma.sync.aligned.m16n8k16.row.col.f32.bf16.bf16.f32 "
        "{%0,%1,%2,%3}, {%4,%5,%6,%7}, {%8,%9}, {%0,%1,%2,%3};"
        : "+f"(d[0]), "+f"(d[1]), "+f"(d[2]), "+f"(d[3])
        : "r"(a[0]), "r"(a[1]), "r"(a[2]), "r"(a[3]), "r"(b[0]), "r"(b[1]));
}
__device__ __forceinline__ void split2(float x, __nv_bfloat16& hi, __nv_bfloat16& lo){
    hi = __float2bfloat16(x);
    lo = __float2bfloat16(x - __bfloat162float(hi));
}
__device__ __forceinline__ void split4_store(float4 v, __nv_bfloat16* bhi, __nv_bfloat16* blo){
    float xs[4] = {v.x, v.y, v.z, v.w};
    uint32_t h[4], l[4];
    #pragma unroll
    for (int i = 0; i < 4; i++){
        __nv_bfloat16 hb, lb; split2(xs[i], hb, lb);
        h[i] = (uint32_t)__bfloat16_as_ushort(hb);
        l[i] = (uint32_t)__bfloat16_as_ushort(lb);
    }
    *(uint2*)bhi = make_uint2(h[0] | (h[1]<<16), h[2] | (h[3]<<16));
    *(uint2*)blo = make_uint2(l[0] | (l[1]<<16), l[2] | (l[3]<<16));
}

// ---------------- embedding (+ split) ----------------
__global__ void embed_kernel(const int* __restrict__ ids, const float* __restrict__ we,
                             const float* __restrict__ pe, float* __restrict__ out,
                             __nv_bfloat16* __restrict__ outs)
{
    int e = blockIdx.x * blockDim.x + threadIdx.x;
    int n  = e >> 8;
    int hq = (e & 255) << 2;
    int s  = n & (SS - 1);
    int id = ids[n];
    float4 w = *(const float4*)(we + (size_t)id * HH + hq);
    float4 p = *(const float4*)(pe + (size_t)s  * HH + hq);
    float4 v = make_float4(w.x+p.x, w.y+p.y, w.z+p.z, w.w+p.w);
    *(float4*)(out + (size_t)n * HH + hq) = v;
    split4_store(v, outs + (size_t)n*2*HH + hq, outs + (size_t)n*2*HH + HH + hq);
}

// ---------------- weight splitter ----------------
__global__ void split_w(const float* __restrict__ W, __nv_bfloat16* __restrict__ out,
                        int ksh, long ldo, long coff, float sgn, int total)
{
    int i = blockIdx.x * blockDim.x + threadIdx.x;
    if (i >= total) return;
    long K = 1L << ksh;
    long r = i >> ksh;
    long c = i & (K - 1);
    float x = sgn * W[i];
    __nv_bfloat16 hi, lo; split2(x, hi, lo);
    out[r*ldo + coff + c]     = hi;
    out[r*ldo + coff + K + c] = lo;
}

// ---------------- mma.sync GEMM: C[8192 rows x M cols] = A'[.,K'] @ B'[M,K']^T ----------------
struct GArgs {
    const __nv_bfloat16* A; const __nv_bfloat16* B;
    long lda, ldb;
    int k1sh, nst, mode;        // mode 0=BU(gamma) 1=Y 2=F1(gelu+split) 3=F2(bias)
    int amap[6], bmap[6];
    const float* vec;
    float* out0; float* out1;
    __nv_bfloat16* osplit;
};

__global__ __launch_bounds__(256, 2) void mma_gemm(const __grid_constant__ GArgs g)
{
    extern __shared__ char sm[];
    __shared__ float tab[128];
    const uint32_t sbase = smem_u32(sm);
    const int tid = threadIdx.x, lane = tid & 31, wid = tid >> 5;
    const int n0 = blockIdx.y * 128;     // token rows
    const int m0 = blockIdx.x * 128;     // output cols

    if (tid < 128){
        if (g.mode == 0)
            tab[tid] = sqrtf(fmaxf(1.f - expf(-2.f * expf(g.vec[(m0 + tid) & (HH-1)])), 0.f));
        else if (g.mode >= 2)
            tab[tid] = g.vec[m0 + tid];
    }

    // cp.async source/dst mapping: thread -> row tid>>1, two 16B chunks
    const int arow = tid >> 1;
    const int ac0  = (tid & 1) * 2;               // chunk pair base (0 or 2)
    const __nv_bfloat16* gA = g.A + (size_t)(n0 + arow) * g.lda + ac0*8;
    const __nv_bfloat16* gB = g.B + (size_t)(m0 + arow) * g.ldb + ac0*8;
    const uint32_t dA = (uint32_t)(arow*PITCH + ac0*16);
    const uint32_t dB = (uint32_t)(A_BYTES + arow*PITCH + ac0*16);

    const int k1m = (1 << g.k1sh) - 1;
    auto load_stage = [&](int s){
        int k0 = s << 5;                          // BK=32 elements
        int seg = k0 >> g.k1sh;
        long ka = ((long)g.amap[seg] << g.k1sh) + (k0 & k1m);
        long kb = ((long)g.bmap[seg] << g.k1sh) + (k0 & k1m);
        uint32_t base = sbase + (uint32_t)(s & (NSTAGE-1)) * STG_BYTES;
        cpa16(base + dA,      gA + ka);
        cpa16(base + dA + 16, gA + ka + 8);
        cpa16(base + dB,      gB + kb);
        cpa16(base + dB + 16, gB + kb + 8);
        CPA_COMMIT();
    };

    // ldmatrix lane offsets
    const int warp_m = wid & 1, warp_n = wid >> 1;
    const int ra = (lane & 7) + (((lane >> 3) & 1) << 3);
    const int ca = (lane >> 4) * 16;
    const int rb = (lane & 7) + (((lane >> 4) & 1) << 3);
    const int cb = ((lane >> 3) & 1) * 16;
    uint32_t aoff[4], boff[2];
    #pragma unroll
    for (int mt = 0; mt < 4; mt++)
        aoff[mt] = (uint32_t)((warp_m*64 + mt*16 + ra) * PITCH + ca);
    #pragma unroll
    for (int ntp = 0; ntp < 2; ntp++)
        boff[ntp] = (uint32_t)(A_BYTES + (warp_n*32 + ntp*16 + rb) * PITCH + cb);

    float acc[4][4][4];
    #pragma unroll
    for (int i = 0; i < 4; i++)
        #pragma unroll
        for (int j = 0; j < 4; j++)
            #pragma unroll
            for (int r = 0; r < 4; r++) acc[i][j][r] = 0.f;

    for (int s = 0; s < NSTAGE-1; s++) load_stage(s);

    const int nst = g.nst;
    for (int i = 0; i < nst; i++){
        CPA_WAIT2();
        __syncthreads();
        uint32_t sb0 = sbase + (uint32_t)(i & (NSTAGE-1)) * STG_BYTES;
        #pragma unroll
        for (int s = 0; s < 2; s++){             // two k16 steps per stage
            uint32_t a[4][4], b[4][2];
            #pragma unroll
            for (int mt = 0; mt < 4; mt++)
                ldsm4(a[mt][0], a[mt][1], a[mt][2], a[mt][3], sb0 + aoff[mt] + s*32);
            #pragma unroll
            for (int ntp = 0; ntp < 2; ntp++){
                uint32_t r0, r1, r2, r3;
                ldsm4(r0, r1, r2, r3, sb0 + boff[ntp] + s*32);
                b[2*ntp][0] = r0; b[2*ntp][1] = r1;
                b[2*ntp+1][0] = r2; b[2*ntp+1][1] = r3;
            }
            #pragma unroll
            for (int mt = 0; mt < 4; mt++)
                #pragma unroll
                for (int nt = 0; nt < 4; nt++)
                    mma16816(acc[mt][nt], a[mt], b[nt]);
        }
        int j = i + NSTAGE - 1;
        if (j < nst) load_stage(j);
        else CPA_COMMIT();
    }

    // epilogue: thread holds rows (base, base+8), col pair (col, col+1) per tile
    const int rbase = n0 + warp_m*64 + (lane >> 2);
    const int cbase = warp_n*32 + (lane & 3)*2;            // col offset within block
    #pragma unroll
    for (int mt = 0; mt < 4; mt++){
        #pragma unroll
        for (int nt = 0; nt < 4; nt++){
            int cl = cbase + nt*8;                          // local col (even)
            int col = m0 + cl;
            #pragma unroll
            for (int h = 0; h < 2; h++){                    // h=0 row, h=1 row+8
                int row = rbase + mt*16 + h*8;
                float v0 = acc[mt][nt][h*2+0];
                float v1 = acc[mt][nt][h*2+1];
                if (g.mode == 0){
                    float* dst = (col < HH) ? g.out0 : g.out1;
                    int cm = col & (HH-1);
                    *(float2*)(dst + (size_t)row*HH + cm) =
                        make_float2(v0 * tab[cl], v1 * tab[cl+1]);
                } else if (g.mode == 1){
                    *(float2*)(g.out0 + (size_t)row*HH + col) = make_float2(v0, v1);
                } else if (g.mode == 2){
                    float x0 = v0 + tab[cl], x1 = v1 + tab[cl+1];
                    x0 = x0 * normcdff(x0);                 // exact GELU
                    x1 = x1 * normcdff(x1);
                    __nv_bfloat16 h0, l0, h1, l1;
                    split2(x0, h0, l0); split2(x1, h1, l1);
                    uint32_t hw = (uint32_t)__bfloat16_as_ushort(h0) | ((uint32_t)__bfloat16_as_ushort(h1) << 16);
                    uint32_t lw = (uint32_t)__bfloat16_as_ushort(l0) | ((uint32_t)__bfloat16_as_ushort(l1) << 16);
                    size_t bh = (size_t)row * (2*FF) + col;
                    *(uint32_t*)(g.osplit + bh)      = hw;
                    *(uint32_t*)(g.osplit + bh + FF) = lw;
                } else {
                    *(float2*)(g.out0 + (size_t)row*HH + col) =
                        make_float2(v0 + tab[cl], v1 + tab[cl+1]);
                }
            }
        }
    }
}

// ---------------- chunked complex scan ----------------
__device__ __forceinline__ void lam_of(const float* nul, const float* thl, int u,
                                       float& lre, float& lim)
{
    float r   = expf(-expf(nul[u]));
    float ang = expf(thl[u]);
    lre = r * cosf(ang);
    lim = r * sinf(ang);
}

__global__ void scan_pass1(const float* __restrict__ nul, const float* __restrict__ thl,
                           float* __restrict__ tre, float* __restrict__ tim,
                           float2* __restrict__ carry)
{
    int t = blockIdx.x * blockDim.x + threadIdx.x;
    int u = t & (HH - 1);
    int rest = t >> 10;
    int c = rest & (NCHUNK - 1);
    int b = rest >> 5;
    float lre, lim; lam_of(nul, thl, u, lre, lim);
    size_t base = ((size_t)b * SS + (size_t)c * CLEN) * HH + u;
    float sre = 0.f, sim = 0.f;
    #pragma unroll 4
    for (int i = 0; i < CLEN; i++) {
        size_t ix = base + (size_t)i * HH;
        float xr = tre[ix], xi = tim[ix];
        float nr = fmaf(lre, sre, fmaf(-lim, sim, xr));
        float ni = fmaf(lre, sim, fmaf( lim, sre, xi));
        sre = nr; sim = ni;
        tre[ix] = sre; tim[ix] = sim;
    }
    carry[(b * NCHUNK + c) * HH + u] = make_float2(sre, sim);
}

__global__ void scan_pass2(const float* __restrict__ nul, const float* __restrict__ thl,
                           float2* __restrict__ carry)
{
    int t = blockIdx.x * blockDim.x + threadIdx.x;
    int u = t & (HH - 1);
    int b = t >> 10;
    float lre, lim; lam_of(nul, thl, u, lre, lim);
    float pr = 1.f, pi = 0.f;
    #pragma unroll
    for (int i = 0; i < CLEN; i++) {
        float nr = pr * lre - pi * lim;
        float ni = pr * lim + pi * lre;
        pr = nr; pi = ni;
    }
    float cre = 0.f, cim = 0.f;
    for (int c = 0; c < NCHUNK; c++) {
        int ix = (b * NCHUNK + c) * HH + u;
        float2 f = carry[ix];
        carry[ix] = make_float2(cre, cim);
        float nr = fmaf(pr, cre, fmaf(-pi, cim, f.x));
        float ni = fmaf(pr, cim, fmaf( pi, cre, f.y));
        cre = nr; cim = ni;
    }
}

// pass3: add carry, emit bf16 splits [re_hi|re_lo|im_hi|im_lo]
__global__ void scan_pass3(const float* __restrict__ nul, const float* __restrict__ thl,
                           const float* __restrict__ tre, const float* __restrict__ tim,
                           const float2* __restrict__ carry, __nv_bfloat16* __restrict__ sp)
{
    int t = blockIdx.x * blockDim.x + threadIdx.x;
    int u = t & (HH - 1);
    int rest = t >> 10;
    int c = rest & (NCHUNK - 1);
    int b = rest >> 5;
    float2 cc = carry[(b * NCHUNK + c) * HH + u];
    float lre, lim; lam_of(nul, thl, u, lre, lim);
    size_t base = ((size_t)b * SS + (size_t)c * CLEN) * HH + u;
    size_t nbase = (size_t)b * SS + (size_t)c * CLEN;
    float pr = lre, pi = lim;
    for (int i = 0; i < CLEN; i++) {
        size_t ix = base + (size_t)i * HH;
        float ar = fmaf(pr, cc.x, fmaf(-pi, cc.y, tre[ix]));
        float ai = fmaf(pr, cc.y, fmaf( pi, cc.x, tim[ix]));
        size_t ro = (nbase + i) * (4*HH) + u;
        __nv_bfloat16 h1, l1, h2, l2;
        split2(ar, h1, l1); split2(ai, h2, l2);
        sp[ro]        = h1;
        sp[ro + HH]   = l1;
        sp[ro + 2*HH] = h2;
        sp[ro + 3*HH] = l2;
        float nr = pr * lre - pi * lim;
        float ni = pr * lim + pi * lre;
        pr = nr; pi = ni;
    }
}

// ---------------- fused residual + RMS-LN (+ split output) ----------------
__global__ void ln_kernel(const float* __restrict__ h, const float* __restrict__ y,
                          const float* __restrict__ Dl, const float* __restrict__ bias,
                          float* __restrict__ out, __nv_bfloat16* __restrict__ osplit)
{
    int n = blockIdx.x;
    int t = threadIdx.x;
    size_t idx = (size_t)n * HH + (t << 2);
    float4 hv = *(const float4*)(h + idx);
    float4 yv = *(const float4*)(y + idx);
    float4 z;
    if (Dl) {
        float4 dv = *(const float4*)(Dl + (t << 2));
        z.x = fmaf(hv.x, 1.f + dv.x, yv.x);
        z.y = fmaf(hv.y, 1.f + dv.y, yv.y);
        z.z = fmaf(hv.z, 1.f + dv.z, yv.z);
        z.w = fmaf(hv.w, 1.f + dv.w, yv.w);
    } else {
        z.x = hv.x + yv.x; z.y = hv.y + yv.y; z.z = hv.z + yv.z; z.w = hv.w + yv.w;
    }
    float s = z.x*z.x + z.y*z.y + z.z*z.z + z.w*z.w;
    #pragma unroll
    for (int o = 16; o; o >>= 1) s += __shfl_xor_sync(0xffffffffu, s, o);
    __shared__ float red[8];
    if ((t & 31) == 0) red[t >> 5] = s;
    __syncthreads();
    float tot = red[0]+red[1]+red[2]+red[3]+red[4]+red[5]+red[6]+red[7];
    float inv = rsqrtf(tot * (1.f / (float)HH) + 1e-12f);
    float4 bv = *(const float4*)(bias + (t << 2));
    float4 o4 = make_float4(fmaf(z.x, inv, bv.x), fmaf(z.y, inv, bv.y),
                            fmaf(z.z, inv, bv.z), fmaf(z.w, inv, bv.w));
    *(float4*)(out + idx) = o4;
    split4_store(o4, osplit + (size_t)n*2*HH + (t<<2),
                     osplit + (size_t)n*2*HH + HH + (t<<2));
}

// ---------------- launch ----------------
extern "C" void kernel_launch(void* const* d_in, const int* in_sizes, int n_in,
                              void* d_out, int out_size)
{
    const int*   ids = (const int*)  d_in[0];
    const float* we  = (const float*)d_in[1];
    const float* pe  = (const float*)d_in[2];
    const float* nu  = (const float*)d_in[3];
    const float* th  = (const float*)d_in[4];
    const float* Bre = (const float*)d_in[5];
    const float* Bim = (const float*)d_in[6];
    const float* Cre = (const float*)d_in[7];
    const float* Cim = (const float*)d_in[8];
    const float* Dp  = (const float*)d_in[9];
    const float* rnb = (const float*)d_in[10];
    const float* w1  = (const float*)d_in[11];
    const float* b1  = (const float*)d_in[12];
    const float* w2  = (const float*)d_in[13];
    const float* b2  = (const float*)d_in[14];
    const float* fnb = (const float*)d_in[15];
    float* out = (float*)d_out;

    float *ph, *ptre, *ptim, *py; float2* pc;
    __nv_bfloat16 *phs, *psp, *pfs, *pwbu, *pwy, *pwf1, *pwf2;
    cudaGetSymbolAddress((void**)&ph,   g_h);
    cudaGetSymbolAddress((void**)&ptre, g_tre);
    cudaGetSymbolAddress((void**)&ptim, g_tim);
    cudaGetSymbolAddress((void**)&py,   g_y);
    cudaGetSymbolAddress((void**)&pc,   g_carry);
    cudaGetSymbolAddress((void**)&phs,  g_hs);
    cudaGetSymbolAddress((void**)&psp,  g_sp);
    cudaGetSymbolAddress((void**)&pfs,  g_fs);
    cudaGetSymbolAddress((void**)&pwbu, g_wbu);
    cudaGetSymbolAddress((void**)&pwy,  g_wy);
    cudaGetSymbolAddress((void**)&pwf1, g_wf1);
    cudaGetSymbolAddress((void**)&pwf2, g_wf2);

    cudaFuncSetAttribute(mma_gemm, cudaFuncAttributeMaxDynamicSharedMemorySize, SMEM_SZ);

    // weight splits (hi|lo) bf16
    for (int l = 0; l < LL; l++) {
        size_t hh = (size_t)HH*HH;
        split_w<<<HH*HH/256, 256>>>(Bre + l*hh, pwbu + (size_t)l*2048*2048,              10, 2048, 0,    1.f, HH*HH);
        split_w<<<HH*HH/256, 256>>>(Bim + l*hh, pwbu + (size_t)l*2048*2048 + 1024L*2048, 10, 2048, 0,    1.f, HH*HH);
        split_w<<<HH*HH/256, 256>>>(Cre + l*hh, pwy  + (size_t)l*1024*4096,              10, 4096, 0,    1.f, HH*HH);
        split_w<<<HH*HH/256, 256>>>(Cim + l*hh, pwy  + (size_t)l*1024*4096,              10, 4096, 2048,-1.f, HH*HH);
        split_w<<<FF*HH/256, 256>>>(w1 + (size_t)l*FF*HH, pwf1 + (size_t)l*4096*2048,    10, 2048, 0,    1.f, FF*HH);
        split_w<<<FF*HH/256, 256>>>(w2 + (size_t)l*HH*FF, pwf2 + (size_t)l*1024*8192,    12, 8192, 0,    1.f, HH*FF);
    }

    embed_kernel<<<(size_t)NN*HH/4/256, 256>>>(ids, we, pe, ph, phs);

    int am1[6] = {0,0,1,0,0,0}, bm1[6] = {0,1,0,0,0,0};          // 3-seg: hihi, hilo, lohi
    int am2[6] = {0,0,1,2,2,3}, bm2[6] = {0,1,0,2,3,2};          // 6-seg complex

    for (int l = 0; l < LL; l++) {
        const float* nul = nu + l*HH;
        const float* thl = th + l*HH;

        // BU: [h_hi|h_lo] x [Bre;Bim] -> tre/tim (gamma fused). M=2048, K'=3072
        GArgs a = {};
        a.A = phs; a.B = pwbu + (size_t)l*2048*2048;
        a.lda = 2048; a.ldb = 2048;
        a.k1sh = 10; a.nst = 96; a.mode = 0;
        for (int i = 0; i < 6; i++){ a.amap[i] = am1[i]; a.bmap[i] = bm1[i]; }
        a.vec = nul; a.out0 = ptre; a.out1 = ptim;
        mma_gemm<<<dim3(16, 64), 256, SMEM_SZ>>>(a);

        scan_pass1<<<BB*NCHUNK*HH/256, 256>>>(nul, thl, ptre, ptim, pc);
        scan_pass2<<<BB*HH/256, 256>>>(nul, thl, pc);
        scan_pass3<<<BB*NCHUNK*HH/256, 256>>>(nul, thl, ptre, ptim, pc, psp);

        // Y: [re_hi|re_lo|im_hi|im_lo] x [Cre|-Cim] -> y. M=1024, K'=6144
        a = GArgs{};
        a.A = psp; a.B = pwy + (size_t)l*1024*4096;
        a.lda = 4096; a.ldb = 4096;
        a.k1sh = 10; a.nst = 192; a.mode = 1;
        for (int i = 0; i < 6; i++){ a.amap[i] = am2[i]; a.bmap[i] = bm2[i]; }
        a.out0 = py;
        mma_gemm<<<dim3(8, 64), 256, SMEM_SZ>>>(a);

        ln_kernel<<<NN, 256>>>(ph, py, Dp + l*HH, rnb + l*HH, ph, phs);

        // FFN1: h_split x w1_split -> gelu -> g_fs. M=4096, K'=3072
        a = GArgs{};
        a.A = phs; a.B = pwf1 + (size_t)l*4096*2048;
        a.lda = 2048; a.ldb = 2048;
        a.k1sh = 10; a.nst = 96; a.mode = 2;
        for (int i = 0; i < 6; i++){ a.amap[i] = am1[i]; a.bmap[i] = bm1[i]; }
        a.vec = b1 + l*FF; a.osplit = pfs;
        mma_gemm<<<dim3(32, 64), 256, SMEM_SZ>>>(a);

        // FFN2: g_fs x w2_split + bias -> y. M=1024, K'=12288
        a = GArgs{};
        a.A = pfs; a.B = pwf2 + (size_t)l*1024*8192;
        a.lda = 8192; a.ldb = 8192;
        a.k1sh = 12; a.nst = 384; a.mode = 3;
        for (int i = 0; i < 6; i++){ a.amap[i] = am1[i]; a.bmap[i] = bm1[i]; }
        a.vec = b2 + l*HH; a.out0 = py;
        mma_gemm<<<dim3(8, 64), 256, SMEM_SZ>>>(a);

        float* lnout = (l == LL-1) ? out : ph;
        ln_kernel<<<NN, 256>>>(ph, py, nullptr, fnb + l*HH, lnout, phs);
    }
}